// round 15
// baseline (speedup 1.0000x reference)
#include <cuda_runtime.h>

// Problem constants (fixed by setup_inputs)
#define NQ      512
#define NC      8000
#define DNUM    6
#define DCAT    20
#define NBINS   50
#define DOUT    10
#define CHUNK   1000
#define NCHUNKS 8
#define CPAD    1024
#define NCPAD   (NCHUNKS * CPAD)   // 8192
#define NENT    (NCPAD + NQ)       // 8704

// Collapsed encoding: 6 bin-sum (G) dims + 20 cat = 26 real dims.
// L1 dist via  sum|x-c| = Sx + Sc - 2*sum(min(x,c))  (min-trick).
// G dims are integers (exact); cat part adds ~1e-4 abs error (tol 1e-3).
#define DDIM 26
#define DROW 27                    // +1 smem row for per-entity sums
#define TQ   16
#define TC   256
#define NBLK ((NQ / TQ) * NCHUNKS) // 256 blocks

#define PADVAL 1e7f

// Scratch (device globals; no allocations allowed)
__device__ float    g_cE[DDIM][NCPAD];  // candidate encodings, chunk-padded
__device__ float    g_xE[DDIM][NQ];     // query encodings
__device__ int      g_y[NCPAD];
__device__ float    g_logits[NCHUNKS][NQ][DOUT];
__device__ float    g_lse[NCHUNKS][NQ];
__device__ unsigned g_done;             // zero-init; last block resets it

// ---------------------------------------------------------------------------
// Encoder (unchanged from the passing R12 kernel). Range A: (entity, feature,
// slice-of-10-bins) work items with a fast-division path: q = t*rcp_rn(d);
// ceil(q) == ceil(rn(t/d)) unless q is within ~5e-7*|q| of an integer, then
// exact __fdiv_rn fallback. 5 exact-integer partials combined via smem.
// Range B/C: cat transpose, pads, labels. Label dtype detected at runtime
// (jax randint(int64) silently yields int32 without x64): int64 labels 0..9
// have all odd 32-bit words zero.
// ---------------------------------------------------------------------------
#define NSLICE  5
#define SLICEB  (NBINS / NSLICE)                 // 10
#define EBLK    255
#define ABLOCKS ((NENT * DNUM * NSLICE) / EBLK)  // 1024 exact
#define BITEMS  (NCPAD + NQ)                     // 8704
#define BBLOCKS ((BITEMS + EBLK - 1) / EBLK)     // 35

__global__ void encode_kernel(const float* __restrict__ x_num,
                              const float* __restrict__ x_cat,
                              const float* __restrict__ c_num,
                              const float* __restrict__ c_cat,
                              const void*  __restrict__ y_raw,
                              const float* __restrict__ delta,
                              const float* __restrict__ u) {
    const int tid = threadIdx.x;

    if (blockIdx.x < ABLOCKS) {
        __shared__ float s_p[EBLK];
        const int w  = blockIdx.x * EBLK + tid;
        const int ej = w / NSLICE, s = w - ej * NSLICE;
        const int j  = ej / NENT;
        const int e  = ej - j * NENT;
        bool valid = true;
        float x = 0.f;
        if (e < NCPAD) {
            const int ch = e >> 10, idx = e & (CPAD - 1);
            if (idx < CHUNK) x = c_num[(ch * CHUNK + idx) * DNUM + j];
            else valid = false;
        } else {
            x = x_num[(e - NCPAD) * DNUM + j];
        }
        float p = 0.f;
        if (valid) {
            const int b0 = j * NBINS + s * SLICEB;
#pragma unroll
            for (int b = 0; b < SLICEB; ++b) {
                const float dl = __ldg(&delta[b0 + b]);
                const float uu = __ldg(&u[b0 + b]);
                const float t  = __fsub_rn(x, __fmul_rn(uu, dl));
                const float q  = __fmul_rn(t, __frcp_rn(dl));
                const float r  = rintf(q);
                float cl;
                if (fabsf(__fsub_rn(q, r)) < __fmaf_rn(fabsf(q), 5e-7f, 1e-30f)) {
                    cl = ceilf(__fdiv_rn(t, dl));   // exact slow path (rare)
                } else {
                    cl = ceilf(q);                  // provably equal to exact
                }
                p = __fadd_rn(p, cl);
            }
        }
        s_p[tid] = p;
        __syncthreads();
        if (s == 0) {
            float g = s_p[tid] + s_p[tid + 1] + s_p[tid + 2] + s_p[tid + 3] + s_p[tid + 4];
            if (e < NCPAD) g_cE[j][e] = valid ? g : PADVAL;
            else           g_xE[j][e - NCPAD] = g;
        }
        return;
    }

    const int item = (blockIdx.x - ABLOCKS) * EBLK + tid;
    if (item < NCPAD) {
        const int c = item;
        const int ch = c >> 10, idx = c & (CPAD - 1);
        if (idx < CHUNK) {
            const int src = ch * CHUNK + idx;
#pragma unroll
            for (int k = 0; k < DCAT; ++k)
                g_cE[DNUM + k][c] = c_cat[src * DCAT + k];
            const int* p32 = (const int*)y_raw;
            int z = 1;
#pragma unroll
            for (int i = 0; i < 32; ++i)
                if (p32[2 * i + 1] != 0) z = 0;
            const long long* p64 = (const long long*)y_raw;
            g_y[c] = z ? (int)p64[src] : p32[src];
        } else {
#pragma unroll
            for (int k = 0; k < DCAT; ++k) g_cE[DNUM + k][c] = PADVAL;
            g_y[c] = 0;
        }
    } else if (item < BITEMS) {
        const int q = item - NCPAD;
#pragma unroll
        for (int k = 0; k < DCAT; ++k)
            g_xE[DNUM + k][q] = x_cat[q * DCAT + k];
    }
}

// ---------------------------------------------------------------------------
// Main kernel: one block per (16-query tile, chunk). Block = (64, 4) threads.
// 4q x 4c register tile, min-trick mainloop (FMNMX alu + FADD fma).
// Per-entity sums Sx/Sc are computed IN-KERNEL from the staged smem slabs
// (prep kernel fused away). Finalize is fused via a last-block ticket:
// the 256th block to finish sums the 8 chunk slots in fixed order
// (deterministic), applies the logs, writes out, and resets the ticket.
// ---------------------------------------------------------------------------
__global__ __launch_bounds__(256, 2) void nca_main_kernel(float* __restrict__ out) {
    const int tc  = threadIdx.x;                 // 0..63
    const int tq  = threadIdx.y;                 // 0..3
    const int lid = tq * 64 + tc;
    const int q0  = blockIdx.x * TQ;
    const int cb0 = blockIdx.y * CPAD;

    __shared__ float    x_s[DROW][TQ];           // rows 0..25 enc, 26 = Sx
    __shared__ float    c_s[DROW][TC];           // rows 0..25 enc, 26 = Sc
    __shared__ float    red[4][2][4][10];
    __shared__ unsigned s_ticket;

    // Stage query slab once (rows 0..25 -> 104 float4)
    if (lid < DDIM * (TQ / 4)) {
        int dd = lid >> 2, t = lid & 3;
        ((float4*)&x_s[dd][0])[t] = ((const float4*)&g_xE[dd][q0])[t];
    }

    float lg[4][10];
#pragma unroll
    for (int qi = 0; qi < 4; ++qi)
#pragma unroll
        for (int k = 0; k < DOUT; ++k) lg[qi][k] = 0.f;

    for (int t = 0; t < 4; ++t) {
        const int cbase = cb0 + t * TC;
        __syncthreads();   // protect c_s reuse (1st iter: also x_s staging)

        // Stage 26 x 256 slab (1664 float4); lid<16 also compute Sx (t==0)
#pragma unroll
        for (int k = 0; k < 7; ++k) {
            int idx = lid + 256 * k;
            if (idx < DDIM * (TC / 4)) {
                int dd = idx >> 6, jj = idx & 63;
                ((float4*)&c_s[dd][0])[jj] = ((const float4*)&g_cE[dd][cbase])[jj];
            }
        }
        if (t == 0 && lid < TQ) {     // x_s visible since the sync above
            float s = 0.f;
#pragma unroll
            for (int d = 0; d < DDIM; ++d) s += x_s[d][lid];
            x_s[DDIM][lid] = s;
        }
        __syncthreads();

        // Per-candidate sums Sc from the staged slab (one cand per thread)
        {
            float s = 0.f;
#pragma unroll
            for (int d = 0; d < DDIM; ++d) s += c_s[d][lid];
            c_s[DDIM][lid] = s;
        }

        int yv[4];
#pragma unroll
        for (int ci = 0; ci < 4; ++ci) yv[ci] = g_y[cbase + tc * 4 + ci];

        float acc[4][4];
#pragma unroll
        for (int qi = 0; qi < 4; ++qi)
#pragma unroll
            for (int ci = 0; ci < 4; ++ci) acc[qi][ci] = 0.f;

#pragma unroll
        for (int dd = 0; dd < DDIM; ++dd) {
            float4 xv = *(const float4*)&x_s[dd][tq * 4];
            float4 cv = *(const float4*)&c_s[dd][tc * 4];
            float xa[4] = {xv.x, xv.y, xv.z, xv.w};
            float ca[4] = {cv.x, cv.y, cv.z, cv.w};
#pragma unroll
            for (int qi = 0; qi < 4; ++qi)
#pragma unroll
                for (int ci = 0; ci < 4; ++ci)
                    acc[qi][ci] += fminf(xa[qi], ca[ci]);   // FMNMX(alu)+FADD(fma)
        }

        __syncthreads();   // c_s[26] (Sc) writes visible before epilogue reads

        // Epilogue: dist = Sx + Sc - 2*acc, one exp per pair
        float4 sxv = *(const float4*)&x_s[DDIM][tq * 4];
        float4 scv = *(const float4*)&c_s[DDIM][tc * 4];
        float Sx[4] = {sxv.x, sxv.y, sxv.z, sxv.w};
        float Sc[4] = {scv.x, scv.y, scv.z, scv.w};
#pragma unroll
        for (int ci = 0; ci < 4; ++ci) {
            int y = yv[ci];
#pragma unroll
            for (int qi = 0; qi < 4; ++qi) {
                float P = Sx[qi] + Sc[ci];
                float dist = __fmaf_rn(acc[qi][ci], -2.f, P);
                float e = __expf(-dist);        // pad: exp(-2.6e8) -> 0
#pragma unroll
                for (int k = 0; k < DOUT; ++k)
                    lg[qi][k] += (y == k) ? e : 0.f;
            }
        }
    }

    // Warp-level plain-sum reduce across 32 lanes
#pragma unroll
    for (int off = 16; off >= 1; off >>= 1) {
#pragma unroll
        for (int qi = 0; qi < 4; ++qi)
#pragma unroll
            for (int k = 0; k < DOUT; ++k)
                lg[qi][k] += __shfl_xor_sync(0xffffffffu, lg[qi][k], off);
    }

    __syncthreads();
    if ((tc & 31) == 0) {
        int h = tc >> 5;
#pragma unroll
        for (int qi = 0; qi < 4; ++qi)
#pragma unroll
            for (int k = 0; k < DOUT; ++k) red[tq][h][qi][k] = lg[qi][k];
    }
    __syncthreads();
    if (tc == 0) {
#pragma unroll
        for (int qi = 0; qi < 4; ++qi) {
            int q = q0 + tq * 4 + qi;
            float S = 0.f;
#pragma unroll
            for (int k = 0; k < DOUT; ++k) {
                float v = red[tq][0][qi][k] + red[tq][1][qi][k];
                g_logits[blockIdx.y][q][k] = v;
                S += v;
            }
            g_lse[blockIdx.y][q] = logf(S);
        }
    }

    // ---- fused finalize: last block to arrive does the log/combine ----
    __threadfence();
    __syncthreads();
    if (lid == 0) s_ticket = atomicAdd(&g_done, 1u);
    __syncthreads();
    if (s_ticket == NBLK - 1) {
        for (int i = lid; i < NQ * DOUT; i += 256) {
            int q = i / DOUT, k = i - q * DOUT;
            float lsum = 0.f, lse = 0.f;
#pragma unroll
            for (int ch = 0; ch < NCHUNKS; ++ch) {    // fixed order: deterministic
                lsum += g_logits[ch][q][k];
                lse  += g_lse[ch][q];
            }
            out[i] = logf(lsum + 1e-8f) - lse;
        }
        __syncthreads();
        if (lid == 0) g_done = 0;   // reset for next graph replay
    }
}

// ---------------------------------------------------------------------------
extern "C" void kernel_launch(void* const* d_in, const int* in_sizes, int n_in,
                              void* d_out, int out_size) {
    const float* x_num = (const float*)d_in[0];
    const float* x_cat = (const float*)d_in[1];
    const float* c_num = (const float*)d_in[2];
    const float* c_cat = (const float*)d_in[3];
    const void*  c_y   = (const void*)d_in[4];
    const float* delta = (const float*)d_in[5];
    const float* u     = (const float*)d_in[6];
    float* out = (float*)d_out;

    encode_kernel<<<ABLOCKS + BBLOCKS, EBLK>>>(
        x_num, x_cat, c_num, c_cat, c_y, delta, u);
    nca_main_kernel<<<dim3(NQ / TQ, NCHUNKS), dim3(64, 4)>>>(out);
}